// round 8
// baseline (speedup 1.0000x reference)
#include <cuda_runtime.h>
#include <cstdint>

#define N_NODES 100000
#define N_EDGES 1600000
#define NF 128
#define SCAN_B 1024
#define SCAN_NBLK ((N_NODES + SCAN_B - 1) / SCAN_B)   // 98

// Scratch (__device__ globals only; no allocation anywhere).
__device__ float g_h[(size_t)N_NODES * NF];   // h = x @ W
__device__ int   g_cnt[N_NODES];              // edge in-degree (no self loop)
__device__ int   g_excl[N_NODES];             // per-block exclusive scan
__device__ int   g_blksum[SCAN_NBLK];
__device__ int   g_blkoff[SCAN_NBLK];
__device__ int   g_rowptr[N_NODES + 1];
__device__ int   g_cur[N_NODES];              // placement cursors
__device__ int   g_esrc[N_EDGES];             // CSR: src ids grouped by dst
__device__ float g_dinv[N_NODES];
__device__ int   g_is64;                      // 1 if edge_index stored as int64

// ---------------------------------------------------------------------------
// 0) Detect index dtype (int64 values < 100000 -> zero high words).
__global__ void detect_idx_kernel(const int* __restrict__ ei32) {
    if (threadIdx.x == 0) {
        int any_odd_nonzero = 0;
        #pragma unroll
        for (int i = 1; i < 64; i += 2)
            if (ei32[i] != 0) any_odd_nonzero = 1;
        g_is64 = any_odd_nonzero ? 0 : 1;
    }
}

// 1) zero edge counts
__global__ void zero_cnt_kernel() {
    int i = blockIdx.x * blockDim.x + threadIdx.x;
    if (i < N_NODES) g_cnt[i] = 0;
}

// 2) count in-degree over edges (dst row)
__global__ __launch_bounds__(256) void count_deg_kernel(const int* __restrict__ ei32) {
    const int stride = g_is64 ? 2 : 1;
    const long long dstbase = g_is64 ? (2LL * N_EDGES) : (long long)N_EDGES;
    int base = 4 * (blockIdx.x * blockDim.x + threadIdx.x);
    #pragma unroll
    for (int j = 0; j < 4; j++) {
        int e = base + j;
        if (e < N_EDGES)
            atomicAdd(&g_cnt[ei32[dstbase + (long long)stride * e]], 1);
    }
}

// 3a) per-block inclusive scan -> exclusive + block sums
__global__ __launch_bounds__(SCAN_B) void scan_a_kernel() {
    __shared__ int sd[SCAN_B];
    const int tid = threadIdx.x;
    const int i = blockIdx.x * SCAN_B + tid;
    int v = (i < N_NODES) ? g_cnt[i] : 0;
    sd[tid] = v;
    __syncthreads();
    #pragma unroll
    for (int off = 1; off < SCAN_B; off <<= 1) {
        int t = (tid >= off) ? sd[tid - off] : 0;
        __syncthreads();
        sd[tid] += t;
        __syncthreads();
    }
    if (i < N_NODES) g_excl[i] = sd[tid] - v;
    if (tid == SCAN_B - 1) g_blksum[blockIdx.x] = sd[tid];
}

// 3b) serial scan of 98 block sums (trivial)
__global__ void scan_b_kernel() {
    if (threadIdx.x == 0) {
        int run = 0;
        for (int k = 0; k < SCAN_NBLK; k++) { g_blkoff[k] = run; run += g_blksum[k]; }
    }
}

// 3c) finalize rowptr / cursors / dinv
__global__ void scan_c_kernel() {
    int i = blockIdx.x * blockDim.x + threadIdx.x;
    if (i < N_NODES) {
        int rp = g_excl[i] + g_blkoff[i >> 10];
        g_rowptr[i] = rp;
        g_cur[i] = rp;
        g_dinv[i] = rsqrtf((float)(g_cnt[i] + 1));   // +1 self loop
        if (i == 0) g_rowptr[N_NODES] = N_EDGES;
    }
}

// 4) placement: CSR src list grouped by dst
__global__ __launch_bounds__(256) void place_kernel(const int* __restrict__ ei32) {
    const int stride = g_is64 ? 2 : 1;
    const long long dstbase = g_is64 ? (2LL * N_EDGES) : (long long)N_EDGES;
    int base = 4 * (blockIdx.x * blockDim.x + threadIdx.x);
    #pragma unroll
    for (int j = 0; j < 4; j++) {
        int e = base + j;
        if (e < N_EDGES) {
            int s = ei32[(long long)stride * e];
            int d = ei32[dstbase + (long long)stride * e];
            int slot = atomicAdd(&g_cur[d], 1);
            g_esrc[slot] = s;
        }
    }
}

// ---------------------------------------------------------------------------
// 5) GEMM: g_h = x @ W.  k-outer with 16 register accumulators per thread.
//    Per k: 1 hot W LDG + broadcast LDS of xsT[k][*] + 16 FFMA  -> FFMA-bound.
#define GEMM_ROWS 16
__global__ __launch_bounds__(128) void gemm_kernel(
    const float* __restrict__ x, const float* __restrict__ W)
{
    __shared__ float xsT[NF][GEMM_ROWS + 1];   // +1 pad kills store conflicts
    const int col  = threadIdx.x;              // 0..127
    const int row0 = blockIdx.x * GEMM_ROWS;

    // stage x tile transposed: xsT[k][r] = x[row0+r][k]
    #pragma unroll
    for (int r = 0; r < GEMM_ROWS; r++)
        xsT[col][r] = x[(size_t)(row0 + r) * NF + col];
    __syncthreads();

    float acc[GEMM_ROWS];
    #pragma unroll
    for (int r = 0; r < GEMM_ROWS; r++) acc[r] = 0.0f;

    #pragma unroll 8
    for (int k = 0; k < NF; k++) {
        const float wk = W[(size_t)k * NF + col];
        #pragma unroll
        for (int r = 0; r < GEMM_ROWS; r++)
            acc[r] = fmaf(xsT[k][r], wk, acc[r]);
    }

    #pragma unroll
    for (int r = 0; r < GEMM_ROWS; r++)
        g_h[(size_t)(row0 + r) * NF + col] = acc[r];
}

// ---------------------------------------------------------------------------
// 6) Gather: one block per dst node, thread = feature column. No atomics.
//    4-way unrolled neighbor loop with independent accumulators (MLP=4).
#define ETILE 128
__global__ __launch_bounds__(128) void gather_kernel(
    const float* __restrict__ b, float* __restrict__ out)
{
    __shared__ int   ss[ETILE];
    __shared__ float sv[ETILE];

    const int d = blockIdx.x;
    const int c = threadIdx.x;
    const int start = g_rowptr[d];
    const int end   = g_rowptr[d + 1];
    const float dinv_d = g_dinv[d];

    float a0 = dinv_d * g_h[(size_t)d * NF + c];   // self loop
    float a1 = 0.0f, a2 = 0.0f, a3 = 0.0f;

    for (int t = start; t < end; t += ETILE) {
        const int n = min(ETILE, end - t);
        if (c < n) {
            int s = g_esrc[t + c];
            ss[c] = s;
            sv[c] = g_dinv[s];
        }
        __syncthreads();
        int j = 0;
        for (; j + 4 <= n; j += 4) {
            a0 = fmaf(g_h[(size_t)ss[j + 0] * NF + c], sv[j + 0], a0);
            a1 = fmaf(g_h[(size_t)ss[j + 1] * NF + c], sv[j + 1], a1);
            a2 = fmaf(g_h[(size_t)ss[j + 2] * NF + c], sv[j + 2], a2);
            a3 = fmaf(g_h[(size_t)ss[j + 3] * NF + c], sv[j + 3], a3);
        }
        for (; j < n; j++)
            a0 = fmaf(g_h[(size_t)ss[j] * NF + c], sv[j], a0);
        __syncthreads();
    }

    const float acc = (a0 + a1) + (a2 + a3);
    out[(size_t)d * NF + c] = b[c] + dinv_d * acc;
}

// ---------------------------------------------------------------------------
extern "C" void kernel_launch(void* const* d_in, const int* in_sizes, int n_in,
                              void* d_out, int out_size) {
    const float* x    = (const float*)d_in[0];   // [N_NODES, NF]
    const int*   ei32 = (const int*)d_in[1];     // [2, N_EDGES] int32 or int64
    const float* W    = (const float*)d_in[2];   // [NF, NF]
    const float* b    = (const float*)d_in[3];   // [NF]
    float*       out  = (float*)d_out;           // [N_NODES, NF]

    detect_idx_kernel<<<1, 32>>>(ei32);
    zero_cnt_kernel<<<(N_NODES + 255) / 256, 256>>>();
    count_deg_kernel<<<(N_EDGES / 4 + 255) / 256, 256>>>(ei32);
    scan_a_kernel<<<SCAN_NBLK, SCAN_B>>>();
    scan_b_kernel<<<1, 32>>>();
    scan_c_kernel<<<(N_NODES + 255) / 256, 256>>>();
    place_kernel<<<(N_EDGES / 4 + 255) / 256, 256>>>(ei32);
    gemm_kernel<<<N_NODES / GEMM_ROWS, 128>>>(x, W);
    gather_kernel<<<N_NODES, 128>>>(b, out);
}

// round 9
// speedup vs baseline: 1.0289x; 1.0289x over previous
#include <cuda_runtime.h>
#include <cstdint>

#define N_NODES 100000
#define N_EDGES 1600000
#define NF 128
#define SCAN_B 1024
#define SCAN_NBLK ((N_NODES + SCAN_B - 1) / SCAN_B)   // 98

// Scratch (__device__ globals only; no allocation anywhere).
__device__ float g_h[(size_t)N_NODES * NF];   // h = x @ W
__device__ int   g_cnt[N_NODES];              // edge in-degree (no self loop)
__device__ int   g_excl[N_NODES];             // per-block exclusive scan
__device__ int   g_blksum[SCAN_NBLK];
__device__ int   g_blkoff[SCAN_NBLK];
__device__ int   g_rowptr[N_NODES + 1];
__device__ int   g_cur[N_NODES];              // placement cursors
__device__ int   g_esrc[N_EDGES];             // CSR: src ids grouped by dst
__device__ float g_dinv[N_NODES];
__device__ int   g_is64;                      // 1 if edge_index stored as int64

// ---------------------------------------------------------------------------
// 0) Detect index dtype (int64 values < 100000 -> zero high words).
__global__ void detect_idx_kernel(const int* __restrict__ ei32) {
    if (threadIdx.x == 0) {
        int any_odd_nonzero = 0;
        #pragma unroll
        for (int i = 1; i < 64; i += 2)
            if (ei32[i] != 0) any_odd_nonzero = 1;
        g_is64 = any_odd_nonzero ? 0 : 1;
    }
}

// 1) zero edge counts
__global__ void zero_cnt_kernel() {
    int i = blockIdx.x * blockDim.x + threadIdx.x;
    if (i < N_NODES) g_cnt[i] = 0;
}

// 2) count in-degree over edges (dst row)
__global__ __launch_bounds__(256) void count_deg_kernel(const int* __restrict__ ei32) {
    const int stride = g_is64 ? 2 : 1;
    const long long dstbase = g_is64 ? (2LL * N_EDGES) : (long long)N_EDGES;
    int base = 4 * (blockIdx.x * blockDim.x + threadIdx.x);
    #pragma unroll
    for (int j = 0; j < 4; j++) {
        int e = base + j;
        if (e < N_EDGES)
            atomicAdd(&g_cnt[ei32[dstbase + (long long)stride * e]], 1);
    }
}

// 3a) per-block inclusive scan -> exclusive + block sums
__global__ __launch_bounds__(SCAN_B) void scan_a_kernel() {
    __shared__ int sd[SCAN_B];
    const int tid = threadIdx.x;
    const int i = blockIdx.x * SCAN_B + tid;
    int v = (i < N_NODES) ? g_cnt[i] : 0;
    sd[tid] = v;
    __syncthreads();
    #pragma unroll
    for (int off = 1; off < SCAN_B; off <<= 1) {
        int t = (tid >= off) ? sd[tid - off] : 0;
        __syncthreads();
        sd[tid] += t;
        __syncthreads();
    }
    if (i < N_NODES) g_excl[i] = sd[tid] - v;
    if (tid == SCAN_B - 1) g_blksum[blockIdx.x] = sd[tid];
}

// 3b) serial scan of 98 block sums (trivial)
__global__ void scan_b_kernel() {
    if (threadIdx.x == 0) {
        int run = 0;
        for (int k = 0; k < SCAN_NBLK; k++) { g_blkoff[k] = run; run += g_blksum[k]; }
    }
}

// 3c) finalize rowptr / cursors / dinv
__global__ void scan_c_kernel() {
    int i = blockIdx.x * blockDim.x + threadIdx.x;
    if (i < N_NODES) {
        int rp = g_excl[i] + g_blkoff[i >> 10];
        g_rowptr[i] = rp;
        g_cur[i] = rp;
        g_dinv[i] = rsqrtf((float)(g_cnt[i] + 1));   // +1 self loop
        if (i == 0) g_rowptr[N_NODES] = N_EDGES;
    }
}

// 4) placement: CSR src list grouped by dst
__global__ __launch_bounds__(256) void place_kernel(const int* __restrict__ ei32) {
    const int stride = g_is64 ? 2 : 1;
    const long long dstbase = g_is64 ? (2LL * N_EDGES) : (long long)N_EDGES;
    int base = 4 * (blockIdx.x * blockDim.x + threadIdx.x);
    #pragma unroll
    for (int j = 0; j < 4; j++) {
        int e = base + j;
        if (e < N_EDGES) {
            int s = ei32[(long long)stride * e];
            int d = ei32[dstbase + (long long)stride * e];
            int slot = atomicAdd(&g_cur[d], 1);
            g_esrc[slot] = s;
        }
    }
}

// ---------------------------------------------------------------------------
// 5) GEMM: g_h = x @ W with packed f32x2 FMA (2 FMAs/instr, PTX-only on
//    sm_103a). Row-pair packing: 32 rows/block, thread = 1 column,
//    16 f32x2 accumulators. Shared x-tile transposed, stride 34 (even ->
//    8B-aligned row pairs for LDS.64; broadcast reads are conflict-free).
#define GROWS 32
__global__ __launch_bounds__(128) void gemm_kernel(
    const float* __restrict__ x, const float* __restrict__ W)
{
    __shared__ float xsT[NF][GROWS + 2];       // stride 34 words
    const int col  = threadIdx.x;              // 0..127
    const int row0 = blockIdx.x * GROWS;

    // stage transposed: xsT[k][r] = x[row0+r][k]  (coalesced LDG over k=col)
    #pragma unroll
    for (int r = 0; r < GROWS; r++)
        xsT[col][r] = x[(size_t)(row0 + r) * NF + col];
    __syncthreads();

    unsigned long long acc[GROWS / 2];
    #pragma unroll
    for (int p = 0; p < GROWS / 2; p++) acc[p] = 0ull;

    #pragma unroll 4
    for (int k = 0; k < NF; k++) {
        const float wk = W[(size_t)k * NF + col];
        unsigned long long w2;
        asm("mov.b64 %0, {%1, %1};" : "=l"(w2) : "f"(wk));
        const unsigned long long* xp =
            reinterpret_cast<const unsigned long long*>(&xsT[k][0]);
        #pragma unroll
        for (int p = 0; p < GROWS / 2; p++) {
            asm("fma.rn.f32x2 %0, %1, %2, %0;"
                : "+l"(acc[p]) : "l"(xp[p]), "l"(w2));
        }
    }

    #pragma unroll
    for (int p = 0; p < GROWS / 2; p++) {
        float lo, hi;
        asm("mov.b64 {%0, %1}, %2;" : "=f"(lo), "=f"(hi) : "l"(acc[p]));
        g_h[(size_t)(row0 + 2 * p)     * NF + col] = lo;
        g_h[(size_t)(row0 + 2 * p + 1) * NF + col] = hi;
    }
}

// ---------------------------------------------------------------------------
// 6) Gather: one block per dst node, thread = feature column. No atomics.
//    (R7 version — proven 269us config.)
#define ETILE 128
__global__ __launch_bounds__(128) void gather_kernel(
    const float* __restrict__ b, float* __restrict__ out)
{
    __shared__ int   ss[ETILE];
    __shared__ float sv[ETILE];

    const int d = blockIdx.x;
    const int c = threadIdx.x;
    const int start = g_rowptr[d];
    const int end   = g_rowptr[d + 1];
    const float dinv_d = g_dinv[d];

    float acc = dinv_d * g_h[(size_t)d * NF + c];   // self loop

    for (int t = start; t < end; t += ETILE) {
        const int n = min(ETILE, end - t);
        if (c < n) {
            int s = g_esrc[t + c];
            ss[c] = s;
            sv[c] = g_dinv[s];
        }
        __syncthreads();
        for (int j = 0; j < n; j++) {
            acc = fmaf(g_h[(size_t)ss[j] * NF + c], sv[j], acc);
        }
        __syncthreads();
    }

    out[(size_t)d * NF + c] = b[c] + dinv_d * acc;
}

// ---------------------------------------------------------------------------
extern "C" void kernel_launch(void* const* d_in, const int* in_sizes, int n_in,
                              void* d_out, int out_size) {
    const float* x    = (const float*)d_in[0];   // [N_NODES, NF]
    const int*   ei32 = (const int*)d_in[1];     // [2, N_EDGES] int32 or int64
    const float* W    = (const float*)d_in[2];   // [NF, NF]
    const float* b    = (const float*)d_in[3];   // [NF]
    float*       out  = (float*)d_out;           // [N_NODES, NF]

    detect_idx_kernel<<<1, 32>>>(ei32);
    zero_cnt_kernel<<<(N_NODES + 255) / 256, 256>>>();
    count_deg_kernel<<<(N_EDGES / 4 + 255) / 256, 256>>>(ei32);
    // position 4: the ncu capture slot lands here -> profile the GEMM
    gemm_kernel<<<N_NODES / GROWS, 128>>>(x, W);
    scan_a_kernel<<<SCAN_NBLK, SCAN_B>>>();
    scan_b_kernel<<<1, 32>>>();
    scan_c_kernel<<<(N_NODES + 255) / 256, 256>>>();
    place_kernel<<<(N_EDGES / 4 + 255) / 256, 256>>>(ei32);
    gather_kernel<<<N_NODES, 128>>>(b, out);
}

// round 10
// speedup vs baseline: 1.1410x; 1.1089x over previous
#include <cuda_runtime.h>
#include <cstdint>

#define N_NODES 100000
#define N_EDGES 1600000
#define NF 128
#define SCAN_B 1024
#define SCAN_NBLK ((N_NODES + SCAN_B - 1) / SCAN_B)   // 98

// Scratch (__device__ globals only; no allocation anywhere).
__device__ float g_h[(size_t)N_NODES * NF];   // h = x @ W
__device__ int   g_cnt[N_NODES];
__device__ int   g_excl[N_NODES];
__device__ int   g_blksum[SCAN_NBLK];
__device__ int   g_blkoff[SCAN_NBLK];
__device__ int   g_rowptr[N_NODES + 1];
__device__ int   g_cur[N_NODES];
__device__ int   g_esrc[N_EDGES];
__device__ float g_dinv[N_NODES];
__device__ int   g_is64;

// ---------------------------------------------------------------------------
__global__ void detect_idx_kernel(const int* __restrict__ ei32) {
    if (threadIdx.x == 0) {
        int any_odd_nonzero = 0;
        #pragma unroll
        for (int i = 1; i < 64; i += 2)
            if (ei32[i] != 0) any_odd_nonzero = 1;
        g_is64 = any_odd_nonzero ? 0 : 1;
    }
}

__global__ void zero_cnt_kernel() {
    int i = blockIdx.x * blockDim.x + threadIdx.x;
    if (i < N_NODES) g_cnt[i] = 0;
}

__global__ __launch_bounds__(256) void count_deg_kernel(const int* __restrict__ ei32) {
    const int stride = g_is64 ? 2 : 1;
    const long long dstbase = g_is64 ? (2LL * N_EDGES) : (long long)N_EDGES;
    int base = 4 * (blockIdx.x * blockDim.x + threadIdx.x);
    #pragma unroll
    for (int j = 0; j < 4; j++) {
        int e = base + j;
        if (e < N_EDGES)
            atomicAdd(&g_cnt[ei32[dstbase + (long long)stride * e]], 1);
    }
}

__global__ __launch_bounds__(SCAN_B) void scan_a_kernel() {
    __shared__ int sd[SCAN_B];
    const int tid = threadIdx.x;
    const int i = blockIdx.x * SCAN_B + tid;
    int v = (i < N_NODES) ? g_cnt[i] : 0;
    sd[tid] = v;
    __syncthreads();
    #pragma unroll
    for (int off = 1; off < SCAN_B; off <<= 1) {
        int t = (tid >= off) ? sd[tid - off] : 0;
        __syncthreads();
        sd[tid] += t;
        __syncthreads();
    }
    if (i < N_NODES) g_excl[i] = sd[tid] - v;
    if (tid == SCAN_B - 1) g_blksum[blockIdx.x] = sd[tid];
}

__global__ void scan_b_kernel() {
    if (threadIdx.x == 0) {
        int run = 0;
        for (int k = 0; k < SCAN_NBLK; k++) { g_blkoff[k] = run; run += g_blksum[k]; }
    }
}

__global__ void scan_c_kernel() {
    int i = blockIdx.x * blockDim.x + threadIdx.x;
    if (i < N_NODES) {
        int rp = g_excl[i] + g_blkoff[i >> 10];
        g_rowptr[i] = rp;
        g_cur[i] = rp;
        g_dinv[i] = rsqrtf((float)(g_cnt[i] + 1));
        if (i == 0) g_rowptr[N_NODES] = N_EDGES;
    }
}

__global__ __launch_bounds__(256) void place_kernel(const int* __restrict__ ei32) {
    const int stride = g_is64 ? 2 : 1;
    const long long dstbase = g_is64 ? (2LL * N_EDGES) : (long long)N_EDGES;
    int base = 4 * (blockIdx.x * blockDim.x + threadIdx.x);
    #pragma unroll
    for (int j = 0; j < 4; j++) {
        int e = base + j;
        if (e < N_EDGES) {
            int s = ei32[(long long)stride * e];
            int d = ei32[dstbase + (long long)stride * e];
            int slot = atomicAdd(&g_cur[d], 1);
            g_esrc[slot] = s;
        }
    }
}

// ---------------------------------------------------------------------------
// GEMM: g_h = x @ W. Register-tiled f32x2:
//   block 256 thr, tile M=64 x N=128, k-chunks of 32.
//   thread tile 8 rows x 4 cols = 16 f32x2 accumulators (packed along cols).
//   Per k: 1 LDS.128 (W cols) + 8 broadcast LDS.32 (x rows) + 16 FMA2.
#define BM 64
#define KC 32
__global__ __launch_bounds__(256) void gemm_kernel(
    const float* __restrict__ x, const float* __restrict__ W)
{
    __shared__ float xsT[KC][BM + 1];   // stride 65 (odd): conflict-free stores
    __shared__ float ws[KC][NF];

    const int tid = threadIdx.x;
    const int tn  = tid & 31;           // col group: cols 4*tn .. 4*tn+3
    const int tm  = tid >> 5;           // row group: rows 8*tm .. 8*tm+7
    const int row0 = blockIdx.x * BM;

    unsigned long long acc[8][2];
    #pragma unroll
    for (int i = 0; i < 8; i++) { acc[i][0] = 0ull; acc[i][1] = 0ull; }

    for (int k0 = 0; k0 < NF; k0 += KC) {
        // stage x chunk transposed: 64 rows x 32 k  (8 elem/thread)
        #pragma unroll
        for (int t = 0; t < 8; t++) {
            int idx = tid + t * 256;          // 0..2047
            int kk = idx & 31;
            int r  = idx >> 5;
            int rg = row0 + r;
            xsT[kk][r] = (rg < N_NODES) ? x[(size_t)rg * NF + k0 + kk] : 0.0f;
        }
        // stage W chunk: 32 k x 128 cols (16 elem/thread)
        #pragma unroll
        for (int t = 0; t < 16; t++) {
            int idx = tid + t * 256;          // 0..4095
            int k = idx >> 7;
            int c = idx & 127;
            ws[k][c] = W[(size_t)(k0 + k) * NF + c];
        }
        __syncthreads();

        #pragma unroll 8
        for (int kk = 0; kk < KC; kk++) {
            const ulonglong2 wv =
                *reinterpret_cast<const ulonglong2*>(&ws[kk][tn * 4]);
            #pragma unroll
            for (int i = 0; i < 8; i++) {
                const float xv = xsT[kk][tm * 8 + i];
                unsigned long long x2;
                asm("mov.b64 %0, {%1, %1};" : "=l"(x2) : "f"(xv));
                asm("fma.rn.f32x2 %0, %1, %2, %0;"
                    : "+l"(acc[i][0]) : "l"(x2), "l"(wv.x));
                asm("fma.rn.f32x2 %0, %1, %2, %0;"
                    : "+l"(acc[i][1]) : "l"(x2), "l"(wv.y));
            }
        }
        __syncthreads();
    }

    #pragma unroll
    for (int i = 0; i < 8; i++) {
        const int rg = row0 + tm * 8 + i;
        if (rg < N_NODES) {
            float4 v;
            asm("mov.b64 {%0, %1}, %2;" : "=f"(v.x), "=f"(v.y) : "l"(acc[i][0]));
            asm("mov.b64 {%0, %1}, %2;" : "=f"(v.z), "=f"(v.w) : "l"(acc[i][1]));
            *reinterpret_cast<float4*>(&g_h[(size_t)rg * NF + tn * 4]) = v;
        }
    }
}

// ---------------------------------------------------------------------------
// Gather: one block per dst node, thread = feature column. No atomics.
#define ETILE 128
__global__ __launch_bounds__(128) void gather_kernel(
    const float* __restrict__ b, float* __restrict__ out)
{
    __shared__ int   ss[ETILE];
    __shared__ float sv[ETILE];

    const int d = blockIdx.x;
    const int c = threadIdx.x;
    const int start = g_rowptr[d];
    const int end   = g_rowptr[d + 1];
    const float dinv_d = g_dinv[d];

    float acc = dinv_d * g_h[(size_t)d * NF + c];   // self loop

    for (int t = start; t < end; t += ETILE) {
        const int n = min(ETILE, end - t);
        if (c < n) {
            int s = g_esrc[t + c];
            ss[c] = s;
            sv[c] = g_dinv[s];
        }
        __syncthreads();
        for (int j = 0; j < n; j++) {
            acc = fmaf(g_h[(size_t)ss[j] * NF + c], sv[j], acc);
        }
        __syncthreads();
    }

    out[(size_t)d * NF + c] = b[c] + dinv_d * acc;
}

// ---------------------------------------------------------------------------
extern "C" void kernel_launch(void* const* d_in, const int* in_sizes, int n_in,
                              void* d_out, int out_size) {
    const float* x    = (const float*)d_in[0];
    const int*   ei32 = (const int*)d_in[1];
    const float* W    = (const float*)d_in[2];
    const float* b    = (const float*)d_in[3];
    float*       out  = (float*)d_out;

    detect_idx_kernel<<<1, 32>>>(ei32);
    zero_cnt_kernel<<<(N_NODES + 255) / 256, 256>>>();
    count_deg_kernel<<<(N_EDGES / 4 + 255) / 256, 256>>>(ei32);
    // position 4: ncu capture slot -> profile the GEMM
    gemm_kernel<<<(N_NODES + BM - 1) / BM, 256>>>(x, W);
    scan_a_kernel<<<SCAN_NBLK, SCAN_B>>>();
    scan_b_kernel<<<1, 32>>>();
    scan_c_kernel<<<(N_NODES + 255) / 256, 256>>>();
    place_kernel<<<(N_EDGES / 4 + 255) / 256, 256>>>(ei32);
    gather_kernel<<<N_NODES, 128>>>(b, out);
}